// round 14
// baseline (speedup 1.0000x reference)
#include <cuda_runtime.h>
#include <math.h>

#define KS 11
#define TILE 32
#define TYB 8
#define RY 4
#define HR 42   // TILE + 10
#define SP 46   // padded float2 row stride: 368B/row, shift ≡ 4 mod 8 words (bank stagger)

typedef unsigned long long ull;

__device__ __forceinline__ ull pk2(float lo, float hi) {
    ull r; asm("mov.b64 %0,{%1,%2};" : "=l"(r) : "f"(lo), "f"(hi)); return r;
}
__device__ __forceinline__ void upk2(ull v, float& lo, float& hi) {
    asm("mov.b64 {%0,%1},%2;" : "=f"(lo), "=f"(hi) : "l"(v));
}
__device__ __forceinline__ ull fma2(ull a, ull b, ull c) {
    ull d; asm("fma.rn.f32x2 %0,%1,%2,%3;" : "=l"(d) : "l"(a), "l"(b), "l"(c)); return d;
}
__device__ __forceinline__ ull mul2(ull a, ull b) {
    ull d; asm("mul.rn.f32x2 %0,%1,%2;" : "=l"(d) : "l"(a), "l"(b)); return d;
}
__device__ __forceinline__ float frcp(float x) {
    float r; asm("rcp.approx.f32 %0, %1;" : "=f"(r) : "f"(x)); return r;
}
__device__ __forceinline__ void lds2(ull& a, ull& b, const void* p) {
    unsigned addr = (unsigned)__cvta_generic_to_shared(p);
    asm("ld.shared.v2.u64 {%0,%1}, [%2];" : "=l"(a), "=l"(b) : "r"(addr));
}
__device__ __forceinline__ void sts2(void* p, ull a, ull b) {
    unsigned addr = (unsigned)__cvta_generic_to_shared(p);
    asm("st.shared.v2.u64 [%0], {%1,%2};" :: "r"(addr), "l"(a), "l"(b));
}

__device__ constexpr float GW[KS] = {
    0.00102836f, 0.00759866f, 0.03600077f, 0.10936069f, 0.21300566f,
    0.26601190f,
    0.21300566f, 0.10936069f, 0.03600077f, 0.00759866f, 0.00102836f
};
__device__ __forceinline__ ull WPK(const ull* w, int k) {
    return w[k < 6 ? k : 10 - k];
}

// Pyramid scratch in (s,d) float2 form
__device__ float2 g_P0[3538944];
__device__ float2 g_P1[884736];
__device__ float g_acc[5 * 96 * 2];

__global__ void zero_acc_kernel() {
    int i = threadIdx.x;
    if (i < 5 * 96 * 2) g_acc[i] = 0.f;
}

// 4-stream SSIM (s=x+y, d=x-y, ss, dd), packed f32x2, 32x32 tile, RY=4.
// h-pass: warp = 4 rows x 8 lanes, RX=4 outputs/lane, 7 aligned LDS.128/task,
// column-permuted sH (logical col 4j+i -> phys col 8i+j).
__global__ __launch_bounds__(256)
void ssim_kernel(const float* __restrict__ X, const float* __restrict__ Y,
                 const float2* __restrict__ SDin, float2* __restrict__ SDout,
                 int W, int OW, int scale)
{
    __shared__ float2 sSD[HR][SP];
    __shared__ float4 sH[HR][TILE];
    __shared__ float rs[TYB], rc[TYB];

    const int tx = threadIdx.x, ty = threadIdx.y;
    const int t = ty * 32 + tx;
    const int x0 = blockIdx.x * TILE, y0 = blockIdx.y * TILE;
    const int bc = blockIdx.z;
    const bool interior = (x0 + HR <= W) && (y0 + HR <= W);

    // ---- Load input tile with halo ----
    if (SDin) {
        const float2* Sb = SDin + (size_t)bc * W * W;
        if (interior) {
            for (int i = t; i < HR * 21; i += 256) {
                int r = i / 21, cp = (i - r * 21) * 2;
                float4 v = *(const float4*)&Sb[(size_t)(y0 + r) * W + x0 + cp];
                *(float4*)&sSD[r][cp] = v;
            }
        } else {
            for (int idx = t; idx < HR * HR; idx += 256) {
                int r = idx / HR, c = idx - r * HR;
                int gx = x0 + c, gy = y0 + r;
                float2 v = make_float2(0.f, 0.f);
                if (gx < W && gy < W) v = Sb[(size_t)gy * W + gx];
                sSD[r][c] = v;
            }
        }
    } else {
        const float* Xb = X + (size_t)bc * W * W;
        const float* Yb = Y + (size_t)bc * W * W;
        if (interior) {
            for (int i = t; i < HR * 21; i += 256) {
                int r = i / 21, cp = (i - r * 21) * 2;
                size_t o = (size_t)(y0 + r) * W + x0 + cp;
                float2 xv = *(const float2*)(Xb + o);
                float2 yv = *(const float2*)(Yb + o);
                float4 v = make_float4(xv.x + yv.x, xv.x - yv.x,
                                       xv.y + yv.y, xv.y - yv.y);
                *(float4*)&sSD[r][cp] = v;
            }
        } else {
            for (int idx = t; idx < HR * HR; idx += 256) {
                int r = idx / HR, c = idx - r * HR;
                int gx = x0 + c, gy = y0 + r;
                float xv = 0.f, yv = 0.f;
                if (gx < W && gy < W) {
                    size_t o = (size_t)gy * W + gx;
                    xv = Xb[o]; yv = Yb[o];
                }
                sSD[r][c] = make_float2(xv + yv, xv - yv);
            }
        }
    }
    __syncthreads();

    // ---- Fused 2x2 pool into next-scale (s,d) buffer ----
    if (SDout) {
        int W2 = W >> 1;
        int cx = t & 15, cy = t >> 4;
        int gx2 = (x0 >> 1) + cx, gy2 = (y0 >> 1) + cy;
        if (gx2 < W2 && gy2 < W2) {
            float2 a = sSD[2 * cy][2 * cx],     b = sSD[2 * cy][2 * cx + 1];
            float2 c = sSD[2 * cy + 1][2 * cx], d = sSD[2 * cy + 1][2 * cx + 1];
            float2 o;
            o.x = 0.25f * (a.x + b.x + c.x + d.x);
            o.y = 0.25f * (a.y + b.y + c.y + d.y);
            SDout[(size_t)bc * W2 * W2 + (size_t)gy2 * W2 + gx2] = o;
        }
    }

    ull wpk[6];
    #pragma unroll
    for (int k = 0; k < 6; k++) wpk[k] = pk2(GW[k], GW[k]);

    // ---- Horizontal blur: warp = 4 rows x 8 lanes, RX=4 outputs/lane ----
    {
        const int rsub = tx >> 3;       // row within warp quad
        const int j = tx & 7;           // col-group (outputs 4j..4j+3)
        #pragma unroll
        for (int iter = 0; iter < 2; iter++) {
            const int r = iter * 32 + ty * 4 + rsub;
            if (iter == 0 || r < HR) {
                ull as[4], aq[4];
                #pragma unroll
                for (int i = 0; i < 4; i++) { as[i] = 0ULL; aq[i] = 0ULL; }
                #pragma unroll
                for (int m = 0; m < 7; m++) {
                    ull pa, pb;
                    lds2(pa, pb, &sSD[r][4 * j + 2 * m]);
                    ull qa = mul2(pa, pa), qb = mul2(pb, pb);
                    #pragma unroll
                    for (int i = 0; i < 4; i++) {
                        int ka = 2 * m - i;          // tap for pa -> output i
                        int kb = 2 * m + 1 - i;      // tap for pb -> output i
                        if (ka >= 0 && ka < KS) {
                            as[i] = fma2(pa, WPK(wpk, ka), as[i]);
                            aq[i] = fma2(qa, WPK(wpk, ka), aq[i]);
                        }
                        if (kb >= 0 && kb < KS) {
                            as[i] = fma2(pb, WPK(wpk, kb), as[i]);
                            aq[i] = fma2(qb, WPK(wpk, kb), aq[i]);
                        }
                    }
                }
                // logical col 4j+i -> phys col 8i+j
                #pragma unroll
                for (int i = 0; i < 4; i++)
                    sts2(&sH[r][8 * i + j], as[i], aq[i]);
            }
        }
    }
    __syncthreads();

    // ---- Vertical blur + SSIM, RY=4 outputs per thread (permuted columns) ----
    ull amu[RY], asg[RY];
    #pragma unroll
    for (int jj = 0; jj < RY; jj++) { amu[jj] = 0ULL; asg[jj] = 0ULL; }
    const int rbase = ty * RY;
    #pragma unroll
    for (int rr = 0; rr < RY - 1 + KS; rr++) {
        ull p01, p23;
        lds2(p01, p23, &sH[rbase + rr][tx]);
        #pragma unroll
        for (int jj = 0; jj < RY; jj++) {
            int k = rr - jj;
            if (k >= 0 && k < KS) {
                amu[jj] = fma2(p01, WPK(wpk, k), amu[jj]);
                asg[jj] = fma2(p23, WPK(wpk, k), asg[jj]);
            }
        }
    }

    float ssum = 0.f, csum = 0.f;
    const int lc = 4 * (tx & 7) + (tx >> 3);   // phys col tx -> logical col
    const int ox = x0 + lc;
    #pragma unroll
    for (int jj = 0; jj < RY; jj++) {
        int oy = y0 + rbase + jj;
        if (ox < OW && oy < OW) {
            float ms2, md2, bss, bdd;
            upk2(mul2(amu[jj], amu[jj]), ms2, md2);
            upk2(asg[jj], bss, bdd);
            const float C1 = 6.5025f, C2 = 58.5225f;
            float musum  = 0.5f * (ms2 + md2);
            float mu2x   = 0.5f * (ms2 - md2);
            float sqsum  = 0.5f * (bss + bdd);
            float xy2    = 0.5f * (bss - bdd);
            float A  = (xy2 - mu2x) + C2;
            float B  = (sqsum - musum) + C2;
            float Cn = mu2x + C1;
            float D  = musum + C1;
            float inv = frcp(B * D);
            csum += A * D * inv;
            ssum += A * Cn * inv;
        }
    }

    #pragma unroll
    for (int off = 16; off; off >>= 1) {
        ssum += __shfl_down_sync(0xffffffffu, ssum, off);
        csum += __shfl_down_sync(0xffffffffu, csum, off);
    }
    if (tx == 0) { rs[ty] = ssum; rc[ty] = csum; }
    __syncthreads();
    if (t == 0) {
        float a = 0.f, b = 0.f;
        #pragma unroll
        for (int i = 0; i < TYB; i++) { a += rs[i]; b += rc[i]; }
        atomicAdd(&g_acc[(scale * 96 + bc) * 2 + 0], a);
        atomicAdd(&g_acc[(scale * 96 + bc) * 2 + 1], b);
    }
}

__global__ void finalize_kernel(float* __restrict__ out) {
    __shared__ float sh[96];
    const int i = threadIdx.x;
    const float wts[5]  = {0.0448f, 0.2856f, 0.3001f, 0.2363f, 0.1333f};
    const float cnts[5] = {374.f * 374.f, 182.f * 182.f, 86.f * 86.f, 38.f * 38.f, 14.f * 14.f};
    if (i < 96) {
        float p = 1.f;
        #pragma unroll
        for (int s = 0; s < 5; s++) {
            int comp = (s < 4) ? 1 : 0;
            float m = g_acc[(s * 96 + i) * 2 + comp] / cnts[s];
            m = fmaxf(m, 0.f);
            p *= powf(m, wts[s]);
        }
        sh[i] = p;
    }
    __syncthreads();
    if (i == 0) {
        float s = 0.f;
        for (int j = 0; j < 96; j++) s += sh[j];
        out[0] = 1.f - s / 96.f;
    }
}

extern "C" void kernel_launch(void* const* d_in, const int* in_sizes, int n_in,
                              void* d_out, int out_size)
{
    const float* X = (const float*)d_in[0];
    const float* Y = (const float*)d_in[1];
    float* out = (float*)d_out;

    float2 *P0, *P1;
    cudaGetSymbolAddress((void**)&P0, g_P0);
    cudaGetSymbolAddress((void**)&P1, g_P1);

    zero_acc_kernel<<<1, 960>>>();

    dim3 blk(32, TYB);
    auto mkgrid = [](int OW) {
        int g = (OW + TILE - 1) / TILE;
        return dim3(g, g, 96);
    };

    // scale 0: reads X,Y; pools 192^2 (s,d) into P0
    ssim_kernel<<<mkgrid(374), blk>>>(X, Y, nullptr, P0, 384, 374, 0);
    // scale 1: reads P0; pools 96^2 into P1
    ssim_kernel<<<mkgrid(182), blk>>>(nullptr, nullptr, P0, P1, 192, 182, 1);
    // scale 2: reads P1; pools 48^2 into P0
    ssim_kernel<<<mkgrid(86), blk>>>(nullptr, nullptr, P1, P0, 96, 86, 2);
    // scale 3: reads P0; pools 24^2 into P1
    ssim_kernel<<<mkgrid(38), blk>>>(nullptr, nullptr, P0, P1, 48, 38, 3);
    // scale 4: reads P1; no pool
    ssim_kernel<<<mkgrid(14), blk>>>(nullptr, nullptr, P1, nullptr, 24, 14, 4);

    finalize_kernel<<<1, 96>>>(out);
}

// round 15
// speedup vs baseline: 1.0212x; 1.0212x over previous
#include <cuda_runtime.h>
#include <math.h>

#define KS 11
#define TILE 32
#define TYB 8
#define RY 4
#define HR 42   // TILE + 10
#define SP 44   // padded float2 row stride (16B-aligned rows)

typedef unsigned long long ull;

__device__ __forceinline__ ull pk2(float lo, float hi) {
    ull r; asm("mov.b64 %0,{%1,%2};" : "=l"(r) : "f"(lo), "f"(hi)); return r;
}
__device__ __forceinline__ void upk2(ull v, float& lo, float& hi) {
    asm("mov.b64 {%0,%1},%2;" : "=f"(lo), "=f"(hi) : "l"(v));
}
__device__ __forceinline__ ull fma2(ull a, ull b, ull c) {
    ull d; asm("fma.rn.f32x2 %0,%1,%2,%3;" : "=l"(d) : "l"(a), "l"(b), "l"(c)); return d;
}
__device__ __forceinline__ ull mul2(ull a, ull b) {
    ull d; asm("mul.rn.f32x2 %0,%1,%2;" : "=l"(d) : "l"(a), "l"(b)); return d;
}
__device__ __forceinline__ float frcp(float x) {
    float r; asm("rcp.approx.f32 %0, %1;" : "=f"(r) : "f"(x)); return r;
}
__device__ __forceinline__ void lds2(ull& a, ull& b, const void* p) {
    unsigned addr = (unsigned)__cvta_generic_to_shared(p);
    asm("ld.shared.v2.u64 {%0,%1}, [%2];" : "=l"(a), "=l"(b) : "r"(addr));
}
__device__ __forceinline__ void sts2(void* p, ull a, ull b) {
    unsigned addr = (unsigned)__cvta_generic_to_shared(p);
    asm("st.shared.v2.u64 [%0], {%1,%2};" :: "r"(addr), "l"(a), "l"(b));
}

__device__ constexpr float GW[KS] = {
    0.00102836f, 0.00759866f, 0.03600077f, 0.10936069f, 0.21300566f,
    0.26601190f,
    0.21300566f, 0.10936069f, 0.03600077f, 0.00759866f, 0.00102836f
};
__device__ __forceinline__ ull WPK(const ull* w, int k) {
    return w[k < 6 ? k : 10 - k];
}

// Pyramid scratch in (s,d) float2 form
__device__ float2 g_P0[3538944];
__device__ float2 g_P1[884736];
// Accumulators: zero at init; finalize resets them after reading (no zero kernel)
__device__ float g_acc[5 * 96 * 2];

// 4-stream SSIM (s=x+y, d=x-y, ss, dd), packed f32x2, 32x32 tile, RY=4.
// h-pass: warp = 2 rows x 16 lane-pairs, LDS.128, column-permuted sH.
__global__ __launch_bounds__(256)
void ssim_kernel(const float* __restrict__ X, const float* __restrict__ Y,
                 const float2* __restrict__ SDin, float2* __restrict__ SDout,
                 int W, int OW, int scale)
{
    __shared__ float2 sSD[HR][SP];
    __shared__ float4 sH[HR][TILE];
    __shared__ float rs[TYB], rc[TYB];

    const int tx = threadIdx.x, ty = threadIdx.y;
    const int t = ty * 32 + tx;
    const int x0 = blockIdx.x * TILE, y0 = blockIdx.y * TILE;
    const int bc = blockIdx.z;
    const bool interior = (x0 + HR <= W) && (y0 + HR <= W);

    // ---- Load input tile with halo ----
    if (SDin) {
        const float2* Sb = SDin + (size_t)bc * W * W;
        if (interior) {
            for (int i = t; i < HR * 21; i += 256) {
                int r = i / 21, cp = (i - r * 21) * 2;
                float4 v = *(const float4*)&Sb[(size_t)(y0 + r) * W + x0 + cp];
                *(float4*)&sSD[r][cp] = v;
            }
        } else {
            for (int idx = t; idx < HR * HR; idx += 256) {
                int r = idx / HR, c = idx - r * HR;
                int gx = x0 + c, gy = y0 + r;
                float2 v = make_float2(0.f, 0.f);
                if (gx < W && gy < W) v = Sb[(size_t)gy * W + gx];
                sSD[r][c] = v;
            }
        }
    } else {
        const float* Xb = X + (size_t)bc * W * W;
        const float* Yb = Y + (size_t)bc * W * W;
        if (interior) {
            // 11 segments per row: 10 x float4 (4 px) + 1 x float2 (2 px)
            for (int i = t; i < HR * 11; i += 256) {
                int r = i / 11, seg = i - r * 11;
                size_t rowo = (size_t)(y0 + r) * W + x0;
                if (seg < 10) {
                    size_t o = rowo + seg * 4;
                    float4 xv = *(const float4*)(Xb + o);
                    float4 yv = *(const float4*)(Yb + o);
                    float4 v0 = make_float4(xv.x + yv.x, xv.x - yv.x,
                                            xv.y + yv.y, xv.y - yv.y);
                    float4 v1 = make_float4(xv.z + yv.z, xv.z - yv.z,
                                            xv.w + yv.w, xv.w - yv.w);
                    *(float4*)&sSD[r][seg * 4] = v0;
                    *(float4*)&sSD[r][seg * 4 + 2] = v1;
                } else {
                    size_t o = rowo + 40;
                    float2 xv = *(const float2*)(Xb + o);
                    float2 yv = *(const float2*)(Yb + o);
                    float4 v = make_float4(xv.x + yv.x, xv.x - yv.x,
                                           xv.y + yv.y, xv.y - yv.y);
                    *(float4*)&sSD[r][40] = v;
                }
            }
        } else {
            for (int idx = t; idx < HR * HR; idx += 256) {
                int r = idx / HR, c = idx - r * HR;
                int gx = x0 + c, gy = y0 + r;
                float xv = 0.f, yv = 0.f;
                if (gx < W && gy < W) {
                    size_t o = (size_t)gy * W + gx;
                    xv = Xb[o]; yv = Yb[o];
                }
                sSD[r][c] = make_float2(xv + yv, xv - yv);
            }
        }
    }
    __syncthreads();

    // ---- Fused 2x2 pool into next-scale (s,d) buffer ----
    if (SDout) {
        int W2 = W >> 1;
        int cx = t & 15, cy = t >> 4;
        int gx2 = (x0 >> 1) + cx, gy2 = (y0 >> 1) + cy;
        if (gx2 < W2 && gy2 < W2) {
            float2 a = sSD[2 * cy][2 * cx],     b = sSD[2 * cy][2 * cx + 1];
            float2 c = sSD[2 * cy + 1][2 * cx], d = sSD[2 * cy + 1][2 * cx + 1];
            float2 o;
            o.x = 0.25f * (a.x + b.x + c.x + d.x);
            o.y = 0.25f * (a.y + b.y + c.y + d.y);
            SDout[(size_t)bc * W2 * W2 + (size_t)gy2 * W2 + gx2] = o;
        }
    }

    ull wpk[6];
    #pragma unroll
    for (int k = 0; k < 6; k++) wpk[k] = pk2(GW[k], GW[k]);

    // ---- Horizontal blur: warp = 2 rows, lane = (half, col-pair j), RX=2 ----
    {
        const int half = tx >> 4;
        const int j = tx & 15;
        #pragma unroll
        for (int rp = 0; rp < HR / 2; rp += TYB) {
            int p = rp + ty;
            if (p < HR / 2) {
                const int r = 2 * p + half;
                ull s0 = 0ULL, q0 = 0ULL, s1 = 0ULL, q1 = 0ULL;
                #pragma unroll
                for (int m = 0; m < 6; m++) {
                    ull pa, pb;
                    lds2(pa, pb, &sSD[r][2 * j + 2 * m]);
                    ull qa = mul2(pa, pa), qb = mul2(pb, pb);
                    s0 = fma2(pa, WPK(wpk, 2 * m), s0);
                    q0 = fma2(qa, WPK(wpk, 2 * m), q0);
                    s1 = fma2(pb, WPK(wpk, 2 * m), s1);
                    q1 = fma2(qb, WPK(wpk, 2 * m), q1);
                    if (m < 5) {
                        s0 = fma2(pb, WPK(wpk, 2 * m + 1), s0);
                        q0 = fma2(qb, WPK(wpk, 2 * m + 1), q0);
                    }
                    if (m > 0) {
                        s1 = fma2(pa, WPK(wpk, 2 * m - 1), s1);
                        q1 = fma2(qa, WPK(wpk, 2 * m - 1), q1);
                    }
                }
                // logical col 2j -> phys col j ; logical col 2j+1 -> phys col 16+j
                sts2(&sH[r][j], s0, q0);
                sts2(&sH[r][16 + j], s1, q1);
            }
        }
    }
    __syncthreads();

    // ---- Vertical blur + SSIM, RY=4 outputs per thread (permuted columns) ----
    ull amu[RY], asg[RY];
    #pragma unroll
    for (int jj = 0; jj < RY; jj++) { amu[jj] = 0ULL; asg[jj] = 0ULL; }
    const int rbase = ty * RY;
    #pragma unroll
    for (int rr = 0; rr < RY - 1 + KS; rr++) {
        ull p01, p23;
        lds2(p01, p23, &sH[rbase + rr][tx]);
        #pragma unroll
        for (int jj = 0; jj < RY; jj++) {
            int k = rr - jj;
            if (k >= 0 && k < KS) {
                amu[jj] = fma2(p01, WPK(wpk, k), amu[jj]);
                asg[jj] = fma2(p23, WPK(wpk, k), asg[jj]);
            }
        }
    }

    float ssum = 0.f, csum = 0.f;
    const int lc = (tx < 16) ? (2 * tx) : (2 * (tx - 16) + 1);  // logical column
    const int ox = x0 + lc;
    #pragma unroll
    for (int jj = 0; jj < RY; jj++) {
        int oy = y0 + rbase + jj;
        if (ox < OW && oy < OW) {
            float ms2, md2, bss, bdd;
            upk2(mul2(amu[jj], amu[jj]), ms2, md2);
            upk2(asg[jj], bss, bdd);
            const float C1 = 6.5025f, C2 = 58.5225f;
            float musum  = 0.5f * (ms2 + md2);
            float mu2x   = 0.5f * (ms2 - md2);
            float sqsum  = 0.5f * (bss + bdd);
            float xy2    = 0.5f * (bss - bdd);
            float A  = (xy2 - mu2x) + C2;
            float B  = (sqsum - musum) + C2;
            float Cn = mu2x + C1;
            float D  = musum + C1;
            float inv = frcp(B * D);
            csum += A * D * inv;
            ssum += A * Cn * inv;
        }
    }

    #pragma unroll
    for (int off = 16; off; off >>= 1) {
        ssum += __shfl_down_sync(0xffffffffu, ssum, off);
        csum += __shfl_down_sync(0xffffffffu, csum, off);
    }
    if (tx == 0) { rs[ty] = ssum; rc[ty] = csum; }
    __syncthreads();
    if (t == 0) {
        float a = 0.f, b = 0.f;
        #pragma unroll
        for (int i = 0; i < TYB; i++) { a += rs[i]; b += rc[i]; }
        atomicAdd(&g_acc[(scale * 96 + bc) * 2 + 0], a);
        atomicAdd(&g_acc[(scale * 96 + bc) * 2 + 1], b);
    }
}

// Reads g_acc, writes loss, then RESETS g_acc to zero for the next replay.
__global__ void finalize_kernel(float* __restrict__ out) {
    __shared__ float sh[96];
    const int i = threadIdx.x;
    const float wts[5]  = {0.0448f, 0.2856f, 0.3001f, 0.2363f, 0.1333f};
    const float cnts[5] = {374.f * 374.f, 182.f * 182.f, 86.f * 86.f, 38.f * 38.f, 14.f * 14.f};
    if (i < 96) {
        float p = 1.f;
        #pragma unroll
        for (int s = 0; s < 5; s++) {
            int comp = (s < 4) ? 1 : 0;
            float m = g_acc[(s * 96 + i) * 2 + comp] / cnts[s];
            m = fmaxf(m, 0.f);
            p *= powf(m, wts[s]);
        }
        sh[i] = p;
    }
    __syncthreads();          // all reads of g_acc complete
    for (int k = i; k < 5 * 96 * 2; k += 96) g_acc[k] = 0.f;
    if (i == 0) {
        float s = 0.f;
        for (int j = 0; j < 96; j++) s += sh[j];
        out[0] = 1.f - s / 96.f;
    }
}

extern "C" void kernel_launch(void* const* d_in, const int* in_sizes, int n_in,
                              void* d_out, int out_size)
{
    const float* X = (const float*)d_in[0];
    const float* Y = (const float*)d_in[1];
    float* out = (float*)d_out;

    float2 *P0, *P1;
    cudaGetSymbolAddress((void**)&P0, g_P0);
    cudaGetSymbolAddress((void**)&P1, g_P1);

    dim3 blk(32, TYB);
    auto mkgrid = [](int OW) {
        int g = (OW + TILE - 1) / TILE;
        return dim3(g, g, 96);
    };

    // scale 0: reads X,Y; pools 192^2 (s,d) into P0
    ssim_kernel<<<mkgrid(374), blk>>>(X, Y, nullptr, P0, 384, 374, 0);
    // scale 1: reads P0; pools 96^2 into P1
    ssim_kernel<<<mkgrid(182), blk>>>(nullptr, nullptr, P0, P1, 192, 182, 1);
    // scale 2: reads P1; pools 48^2 into P0
    ssim_kernel<<<mkgrid(86), blk>>>(nullptr, nullptr, P1, P0, 96, 86, 2);
    // scale 3: reads P0; pools 24^2 into P1
    ssim_kernel<<<mkgrid(38), blk>>>(nullptr, nullptr, P0, P1, 48, 38, 3);
    // scale 4: reads P1; no pool
    ssim_kernel<<<mkgrid(14), blk>>>(nullptr, nullptr, P1, nullptr, 24, 14, 4);

    finalize_kernel<<<1, 96>>>(out);
}

// round 17
// speedup vs baseline: 1.0253x; 1.0040x over previous
#include <cuda_runtime.h>
#include <math.h>

#define KS 11
#define TILE 32
#define TYB 8
#define RY 4
#define HR 42   // TILE + 10
#define SP 44   // padded float2 row stride (16B-aligned rows)

typedef unsigned long long ull;

__device__ __forceinline__ ull pk2(float lo, float hi) {
    ull r; asm("mov.b64 %0,{%1,%2};" : "=l"(r) : "f"(lo), "f"(hi)); return r;
}
__device__ __forceinline__ void upk2(ull v, float& lo, float& hi) {
    asm("mov.b64 {%0,%1},%2;" : "=f"(lo), "=f"(hi) : "l"(v));
}
__device__ __forceinline__ ull fma2(ull a, ull b, ull c) {
    ull d; asm("fma.rn.f32x2 %0,%1,%2,%3;" : "=l"(d) : "l"(a), "l"(b), "l"(c)); return d;
}
__device__ __forceinline__ ull mul2(ull a, ull b) {
    ull d; asm("mul.rn.f32x2 %0,%1,%2;" : "=l"(d) : "l"(a), "l"(b)); return d;
}
__device__ __forceinline__ float frcp(float x) {
    float r; asm("rcp.approx.f32 %0, %1;" : "=f"(r) : "f"(x)); return r;
}
__device__ __forceinline__ void lds2(ull& a, ull& b, const void* p) {
    unsigned addr = (unsigned)__cvta_generic_to_shared(p);
    asm("ld.shared.v2.u64 {%0,%1}, [%2];" : "=l"(a), "=l"(b) : "r"(addr));
}
__device__ __forceinline__ void sts2(void* p, ull a, ull b) {
    unsigned addr = (unsigned)__cvta_generic_to_shared(p);
    asm("st.shared.v2.u64 [%0], {%1,%2};" :: "r"(addr), "l"(a), "l"(b));
}

__device__ constexpr float GW[KS] = {
    0.00102836f, 0.00759866f, 0.03600077f, 0.10936069f, 0.21300566f,
    0.26601190f,
    0.21300566f, 0.10936069f, 0.03600077f, 0.00759866f, 0.00102836f
};
__device__ __forceinline__ ull WPK(const ull* w, int k) {
    return w[k < 6 ? k : 10 - k];
}

// Pyramid scratch in (s,d) float2 form
__device__ float2 g_P0[3538944];
__device__ float2 g_P1[884736];
// Accumulators: zero at init; finalize resets after reading
__device__ float g_acc[5 * 96 * 2];

__device__ __forceinline__ void ssim_eval(float ms, float md, float bss, float bdd,
                                          float& ss, float& cs)
{
    const float C1 = 6.5025f, C2 = 58.5225f;
    float ms2 = ms * ms, md2 = md * md;
    float musum  = 0.5f * (ms2 + md2);
    float mu2x   = 0.5f * (ms2 - md2);
    float sqsum  = 0.5f * (bss + bdd);
    float xy2    = 0.5f * (bss - bdd);
    float s1s2   = sqsum - musum;
    float sig122 = xy2 - mu2x;
    cs = (sig122 + C2) / (s1s2 + C2);
    ss = ((mu2x + C1) / (musum + C1)) * cs;
}

// ---------- scales 0,1,2 kernel (R15, unchanged) ----------
__global__ __launch_bounds__(256)
void ssim_kernel(const float* __restrict__ X, const float* __restrict__ Y,
                 const float2* __restrict__ SDin, float2* __restrict__ SDout,
                 int W, int OW, int scale)
{
    __shared__ float2 sSD[HR][SP];
    __shared__ float4 sH[HR][TILE];
    __shared__ float rs[TYB], rc[TYB];

    const int tx = threadIdx.x, ty = threadIdx.y;
    const int t = ty * 32 + tx;
    const int x0 = blockIdx.x * TILE, y0 = blockIdx.y * TILE;
    const int bc = blockIdx.z;
    const bool interior = (x0 + HR <= W) && (y0 + HR <= W);

    if (SDin) {
        const float2* Sb = SDin + (size_t)bc * W * W;
        if (interior) {
            for (int i = t; i < HR * 21; i += 256) {
                int r = i / 21, cp = (i - r * 21) * 2;
                float4 v = *(const float4*)&Sb[(size_t)(y0 + r) * W + x0 + cp];
                *(float4*)&sSD[r][cp] = v;
            }
        } else {
            for (int idx = t; idx < HR * HR; idx += 256) {
                int r = idx / HR, c = idx - r * HR;
                int gx = x0 + c, gy = y0 + r;
                float2 v = make_float2(0.f, 0.f);
                if (gx < W && gy < W) v = Sb[(size_t)gy * W + gx];
                sSD[r][c] = v;
            }
        }
    } else {
        const float* Xb = X + (size_t)bc * W * W;
        const float* Yb = Y + (size_t)bc * W * W;
        if (interior) {
            for (int i = t; i < HR * 11; i += 256) {
                int r = i / 11, seg = i - r * 11;
                size_t rowo = (size_t)(y0 + r) * W + x0;
                if (seg < 10) {
                    size_t o = rowo + seg * 4;
                    float4 xv = *(const float4*)(Xb + o);
                    float4 yv = *(const float4*)(Yb + o);
                    float4 v0 = make_float4(xv.x + yv.x, xv.x - yv.x,
                                            xv.y + yv.y, xv.y - yv.y);
                    float4 v1 = make_float4(xv.z + yv.z, xv.z - yv.z,
                                            xv.w + yv.w, xv.w - yv.w);
                    *(float4*)&sSD[r][seg * 4] = v0;
                    *(float4*)&sSD[r][seg * 4 + 2] = v1;
                } else {
                    size_t o = rowo + 40;
                    float2 xv = *(const float2*)(Xb + o);
                    float2 yv = *(const float2*)(Yb + o);
                    float4 v = make_float4(xv.x + yv.x, xv.x - yv.x,
                                           xv.y + yv.y, xv.y - yv.y);
                    *(float4*)&sSD[r][40] = v;
                }
            }
        } else {
            for (int idx = t; idx < HR * HR; idx += 256) {
                int r = idx / HR, c = idx - r * HR;
                int gx = x0 + c, gy = y0 + r;
                float xv = 0.f, yv = 0.f;
                if (gx < W && gy < W) {
                    size_t o = (size_t)gy * W + gx;
                    xv = Xb[o]; yv = Yb[o];
                }
                sSD[r][c] = make_float2(xv + yv, xv - yv);
            }
        }
    }
    __syncthreads();

    if (SDout) {
        int W2 = W >> 1;
        int cx = t & 15, cy = t >> 4;
        int gx2 = (x0 >> 1) + cx, gy2 = (y0 >> 1) + cy;
        if (gx2 < W2 && gy2 < W2) {
            float2 a = sSD[2 * cy][2 * cx],     b = sSD[2 * cy][2 * cx + 1];
            float2 c = sSD[2 * cy + 1][2 * cx], d = sSD[2 * cy + 1][2 * cx + 1];
            float2 o;
            o.x = 0.25f * (a.x + b.x + c.x + d.x);
            o.y = 0.25f * (a.y + b.y + c.y + d.y);
            SDout[(size_t)bc * W2 * W2 + (size_t)gy2 * W2 + gx2] = o;
        }
    }

    ull wpk[6];
    #pragma unroll
    for (int k = 0; k < 6; k++) wpk[k] = pk2(GW[k], GW[k]);

    // h-pass: warp = 2 rows x 16 lane-pairs, LDS.128, column-permuted sH
    {
        const int half = tx >> 4;
        const int j = tx & 15;
        #pragma unroll
        for (int rp = 0; rp < HR / 2; rp += TYB) {
            int p = rp + ty;
            if (p < HR / 2) {
                const int r = 2 * p + half;
                ull s0 = 0ULL, q0 = 0ULL, s1 = 0ULL, q1 = 0ULL;
                #pragma unroll
                for (int m = 0; m < 6; m++) {
                    ull pa, pb;
                    lds2(pa, pb, &sSD[r][2 * j + 2 * m]);
                    ull qa = mul2(pa, pa), qb = mul2(pb, pb);
                    s0 = fma2(pa, WPK(wpk, 2 * m), s0);
                    q0 = fma2(qa, WPK(wpk, 2 * m), q0);
                    s1 = fma2(pb, WPK(wpk, 2 * m), s1);
                    q1 = fma2(qb, WPK(wpk, 2 * m), q1);
                    if (m < 5) {
                        s0 = fma2(pb, WPK(wpk, 2 * m + 1), s0);
                        q0 = fma2(qb, WPK(wpk, 2 * m + 1), q0);
                    }
                    if (m > 0) {
                        s1 = fma2(pa, WPK(wpk, 2 * m - 1), s1);
                        q1 = fma2(qa, WPK(wpk, 2 * m - 1), q1);
                    }
                }
                sts2(&sH[r][j], s0, q0);
                sts2(&sH[r][16 + j], s1, q1);
            }
        }
    }
    __syncthreads();

    ull amu[RY], asg[RY];
    #pragma unroll
    for (int jj = 0; jj < RY; jj++) { amu[jj] = 0ULL; asg[jj] = 0ULL; }
    const int rbase = ty * RY;
    #pragma unroll
    for (int rr = 0; rr < RY - 1 + KS; rr++) {
        ull p01, p23;
        lds2(p01, p23, &sH[rbase + rr][tx]);
        #pragma unroll
        for (int jj = 0; jj < RY; jj++) {
            int k = rr - jj;
            if (k >= 0 && k < KS) {
                amu[jj] = fma2(p01, WPK(wpk, k), amu[jj]);
                asg[jj] = fma2(p23, WPK(wpk, k), asg[jj]);
            }
        }
    }

    float ssum = 0.f, csum = 0.f;
    const int lc = (tx < 16) ? (2 * tx) : (2 * (tx - 16) + 1);
    const int ox = x0 + lc;
    #pragma unroll
    for (int jj = 0; jj < RY; jj++) {
        int oy = y0 + rbase + jj;
        if (ox < OW && oy < OW) {
            float ms2, md2, bss, bdd;
            upk2(mul2(amu[jj], amu[jj]), ms2, md2);
            upk2(asg[jj], bss, bdd);
            const float C1 = 6.5025f, C2 = 58.5225f;
            float musum  = 0.5f * (ms2 + md2);
            float mu2x   = 0.5f * (ms2 - md2);
            float sqsum  = 0.5f * (bss + bdd);
            float xy2    = 0.5f * (bss - bdd);
            float A  = (xy2 - mu2x) + C2;
            float B  = (sqsum - musum) + C2;
            float Cn = mu2x + C1;
            float D  = musum + C1;
            float inv = frcp(B * D);
            csum += A * D * inv;
            ssum += A * Cn * inv;
        }
    }

    #pragma unroll
    for (int off = 16; off; off >>= 1) {
        ssum += __shfl_down_sync(0xffffffffu, ssum, off);
        csum += __shfl_down_sync(0xffffffffu, csum, off);
    }
    if (tx == 0) { rs[ty] = ssum; rc[ty] = csum; }
    __syncthreads();
    if (t == 0) {
        float a = 0.f, b = 0.f;
        #pragma unroll
        for (int i = 0; i < TYB; i++) { a += rs[i]; b += rc[i]; }
        atomicAdd(&g_acc[(scale * 96 + bc) * 2 + 0], a);
        atomicAdd(&g_acc[(scale * 96 + bc) * 2 + 1], b);
    }
}

// ---------- Fused scales 3+4 (verbatim R7 structure, proven correct) ----------
#define S3W 48
#define S3P 49
#define S3OW 38
#define S3HP 41
#define S4W 24
#define S4P 25
#define S4OW 14
#define S4HP 15
#define OFF_SH3 (S3W * S3P * 8)                    // 18816
#define OFF_SPX (OFF_SH3 + S3W * S3HP * 16)        // 50304
#define OFF_SH4 (OFF_SPX + S4W * S4P * 8)          // 55104
#define FUSED_SMEM (OFF_SH4 + S4W * S4HP * 16)     // 60864

__global__ __launch_bounds__(256)
void ssim34_kernel(const float2* __restrict__ SDin)
{
    extern __shared__ char sm[];
    float2 (*sSD3)[S3P] = (float2 (*)[S3P])sm;
    float4 (*sH3)[S3HP] = (float4 (*)[S3HP])(sm + OFF_SH3);
    float2 (*sP)[S4P]   = (float2 (*)[S4P])(sm + OFF_SPX);
    float4 (*sH4)[S4HP] = (float4 (*)[S4HP])(sm + OFF_SH4);
    __shared__ float r3s[8], r3c[8], r4s[8], r4c[8];

    const int t = threadIdx.x;
    const int wid = t >> 5, lane = t & 31;
    const int bc = blockIdx.x;

    ull wpk[KS];
    #pragma unroll
    for (int k = 0; k < KS; k++) wpk[k] = pk2(GW[k], GW[k]);

    const float2* Sb = SDin + (size_t)bc * S3W * S3W;
    for (int idx = t; idx < S3W * S3W; idx += 256) {
        int r = idx / S3W, c = idx - r * S3W;
        sSD3[r][c] = Sb[idx];
    }
    __syncthreads();

    // pool 48^2 -> 24^2 into sP
    for (int idx = t; idx < S4W * S4W; idx += 256) {
        int cy = idx / S4W, cx = idx - cy * S4W;
        float2 a = sSD3[2 * cy][2 * cx],     b = sSD3[2 * cy][2 * cx + 1];
        float2 c = sSD3[2 * cy + 1][2 * cx], d = sSD3[2 * cy + 1][2 * cx + 1];
        float2 o;
        o.x = 0.25f * (a.x + b.x + c.x + d.x);
        o.y = 0.25f * (a.y + b.y + c.y + d.y);
        sP[cy][cx] = o;
    }

    // scale-3 h-pass: rows 48, cols 0..37
    for (int r = wid; r < S3W; r += 8) {
        for (int c = lane; c < S3OW; c += 32) {
            ull a01 = 0ULL, a23 = 0ULL;
            #pragma unroll
            for (int k = 0; k < KS; k++) {
                float2 v = sSD3[r][c + k];
                ull pv = pk2(v.x, v.y);
                a01 = fma2(pv, wpk[k], a01);
                a23 = fma2(mul2(pv, pv), wpk[k], a23);
            }
            float b0, b1, b2, b3;
            upk2(a01, b0, b1); upk2(a23, b2, b3);
            sH3[r][c] = make_float4(b0, b1, b2, b3);
        }
    }
    __syncthreads();

    float s3 = 0.f, c3 = 0.f, s4 = 0.f, c4 = 0.f;

    // scale-3 v-pass + ssim
    for (int idx = t; idx < S3OW * S3OW; idx += 256) {
        int oy = idx / S3OW, ox = idx - oy * S3OW;
        ull a01 = 0ULL, a23 = 0ULL;
        #pragma unroll
        for (int k = 0; k < KS; k++) {
            float4 u = sH3[oy + k][ox];
            a01 = fma2(pk2(u.x, u.y), wpk[k], a01);
            a23 = fma2(pk2(u.z, u.w), wpk[k], a23);
        }
        float ms, md, bss, bdd, ss, cs;
        upk2(a01, ms, md); upk2(a23, bss, bdd);
        ssim_eval(ms, md, bss, bdd, ss, cs);
        s3 += ss; c3 += cs;
    }

    // scale-4 h-pass: rows 24, cols 0..13 (sP written before last sync)
    for (int r = wid; r < S4W; r += 8) {
        if (lane < S4OW) {
            int c = lane;
            ull a01 = 0ULL, a23 = 0ULL;
            #pragma unroll
            for (int k = 0; k < KS; k++) {
                float2 v = sP[r][c + k];
                ull pv = pk2(v.x, v.y);
                a01 = fma2(pv, wpk[k], a01);
                a23 = fma2(mul2(pv, pv), wpk[k], a23);
            }
            float b0, b1, b2, b3;
            upk2(a01, b0, b1); upk2(a23, b2, b3);
            sH4[r][c] = make_float4(b0, b1, b2, b3);
        }
    }
    __syncthreads();

    // scale-4 v-pass + ssim
    for (int idx = t; idx < S4OW * S4OW; idx += 256) {
        int oy = idx / S4OW, ox = idx - oy * S4OW;
        ull a01 = 0ULL, a23 = 0ULL;
        #pragma unroll
        for (int k = 0; k < KS; k++) {
            float4 u = sH4[oy + k][ox];
            a01 = fma2(pk2(u.x, u.y), wpk[k], a01);
            a23 = fma2(pk2(u.z, u.w), wpk[k], a23);
        }
        float ms, md, bss, bdd, ss, cs;
        upk2(a01, ms, md); upk2(a23, bss, bdd);
        ssim_eval(ms, md, bss, bdd, ss, cs);
        s4 += ss; c4 += cs;
    }

    #pragma unroll
    for (int off = 16; off; off >>= 1) {
        s3 += __shfl_down_sync(0xffffffffu, s3, off);
        c3 += __shfl_down_sync(0xffffffffu, c3, off);
        s4 += __shfl_down_sync(0xffffffffu, s4, off);
        c4 += __shfl_down_sync(0xffffffffu, c4, off);
    }
    if (lane == 0) { r3s[wid] = s3; r3c[wid] = c3; r4s[wid] = s4; r4c[wid] = c4; }
    __syncthreads();
    if (t == 0) {
        float a3 = 0.f, b3 = 0.f, a4 = 0.f, b4 = 0.f;
        #pragma unroll
        for (int i = 0; i < 8; i++) { a3 += r3s[i]; b3 += r3c[i]; a4 += r4s[i]; b4 += r4c[i]; }
        g_acc[(3 * 96 + bc) * 2 + 0] = a3;
        g_acc[(3 * 96 + bc) * 2 + 1] = b3;
        g_acc[(4 * 96 + bc) * 2 + 0] = a4;
        g_acc[(4 * 96 + bc) * 2 + 1] = b4;
    }
}

// Reads g_acc, writes loss, resets scales 0-2 accumulators (3,4 are stores)
__global__ void finalize_kernel(float* __restrict__ out) {
    __shared__ float sh[96];
    const int i = threadIdx.x;
    const float wts[5]  = {0.0448f, 0.2856f, 0.3001f, 0.2363f, 0.1333f};
    const float cnts[5] = {374.f * 374.f, 182.f * 182.f, 86.f * 86.f, 38.f * 38.f, 14.f * 14.f};
    if (i < 96) {
        float p = 1.f;
        #pragma unroll
        for (int s = 0; s < 5; s++) {
            int comp = (s < 4) ? 1 : 0;
            float m = g_acc[(s * 96 + i) * 2 + comp] / cnts[s];
            m = fmaxf(m, 0.f);
            p *= powf(m, wts[s]);
        }
        sh[i] = p;
    }
    __syncthreads();
    for (int k = i; k < 5 * 96 * 2; k += 96) g_acc[k] = 0.f;
    if (i == 0) {
        float s = 0.f;
        for (int j = 0; j < 96; j++) s += sh[j];
        out[0] = 1.f - s / 96.f;
    }
}

extern "C" void kernel_launch(void* const* d_in, const int* in_sizes, int n_in,
                              void* d_out, int out_size)
{
    const float* X = (const float*)d_in[0];
    const float* Y = (const float*)d_in[1];
    float* out = (float*)d_out;

    cudaFuncSetAttribute(ssim34_kernel,
                         cudaFuncAttributeMaxDynamicSharedMemorySize, FUSED_SMEM);

    float2 *P0, *P1;
    cudaGetSymbolAddress((void**)&P0, g_P0);
    cudaGetSymbolAddress((void**)&P1, g_P1);

    dim3 blk(32, TYB);
    auto mkgrid = [](int OW) {
        int g = (OW + TILE - 1) / TILE;
        return dim3(g, g, 96);
    };

    // scale 0: reads X,Y; pools 192^2 (s,d) into P0
    ssim_kernel<<<mkgrid(374), blk>>>(X, Y, nullptr, P0, 384, 374, 0);
    // scale 1: reads P0; pools 96^2 into P1
    ssim_kernel<<<mkgrid(182), blk>>>(nullptr, nullptr, P0, P1, 192, 182, 1);
    // scale 2: reads P1; pools 48^2 into P0
    ssim_kernel<<<mkgrid(86), blk>>>(nullptr, nullptr, P1, P0, 96, 86, 2);
    // scales 3+4 fused (proven R7 kernel): reads P0 (48^2)
    ssim34_kernel<<<96, 256, FUSED_SMEM>>>(P0);

    finalize_kernel<<<1, 96>>>(out);
}